// round 1
// baseline (speedup 1.0000x reference)
#include <cuda_runtime.h>
#include <cstdint>

#define B_  64
#define NI  2048
#define DI  16
#define NO  32
#define DO  32
#define CH  16            // i-chunks per (b) for round partials
#define IC  (NI / CH)     // 128 i per chunk

// Scratch (alloc-free rule: __device__ globals)
__device__ float g_uhat[(size_t)B_ * NI * NO * DO];   // [b][i][o][d]  536 MB
__device__ float g_part[B_ * CH * NO * DO];           // per-chunk s partials, 4 MB
__device__ float g_vsum[B_ * NO * DO];                // running sum of v across rounds

// ---------- packed f32x2 helpers (Blackwell FFMA2 via PTX) ----------
__device__ __forceinline__ unsigned long long splat2(float v) {
    unsigned long long r;
    asm("mov.b64 %0, {%1, %1};" : "=l"(r) : "f"(v));
    return r;
}
__device__ __forceinline__ void ffma2(unsigned long long &d,
                                      unsigned long long a, unsigned long long b) {
    asm("fma.rn.f32x2 %0, %1, %2, %0;" : "+l"(d) : "l"(a), "l"(b));
}

// ---------------------------------------------------------------------------
// K1: u_hat[b][i][o][d] = sum_k W[o][i][d][k] * x[b][i][k]
// CTA per i (2048 CTAs, 1024 threads). Thread owns (o,d), loops b in packs of 4
// with f32x2 FMAs (two b's per instruction). Writes coalesced 4KB per b.
// ---------------------------------------------------------------------------
__global__ __launch_bounds__(1024, 1)
void k1_uhat(const float* __restrict__ x, const float* __restrict__ W) {
    const int i = blockIdx.x;
    const int t = threadIdx.x;

    __shared__ __align__(16) float xs[DI][B_];   // [k][b]
    {
        int b = t >> 4, k = t & 15;
        xs[k][b] = x[((size_t)b * NI + i) * DI + k];
    }

    const int o = t >> 5, d = t & 31;
    const float4* wp = reinterpret_cast<const float4*>(W) +
                       ((((size_t)o * NI + i) * DO + d) << 2);   // 16 floats = 4 float4
    float4 wa = wp[0], wb = wp[1], wc = wp[2], wd = wp[3];
    unsigned long long w2[16];
    w2[0]  = splat2(wa.x); w2[1]  = splat2(wa.y); w2[2]  = splat2(wa.z); w2[3]  = splat2(wa.w);
    w2[4]  = splat2(wb.x); w2[5]  = splat2(wb.y); w2[6]  = splat2(wb.z); w2[7]  = splat2(wb.w);
    w2[8]  = splat2(wc.x); w2[9]  = splat2(wc.y); w2[10] = splat2(wc.z); w2[11] = splat2(wc.w);
    w2[12] = splat2(wd.x); w2[13] = splat2(wd.y); w2[14] = splat2(wd.z); w2[15] = splat2(wd.w);

    __syncthreads();

    float* ob = g_uhat + (size_t)i * (NO * DO) + t;
    const size_t bs = (size_t)NI * NO * DO;   // stride per b in floats

    #pragma unroll 1
    for (int b = 0; b < B_; b += 4) {
        unsigned long long a01 = 0ull, a23 = 0ull;   // {0.f, 0.f}
        #pragma unroll
        for (int k = 0; k < 16; k++) {
            unsigned long long x01 =
                *reinterpret_cast<const unsigned long long*>(&xs[k][b]);
            unsigned long long x23 =
                *reinterpret_cast<const unsigned long long*>(&xs[k][b + 2]);
            ffma2(a01, w2[k], x01);
            ffma2(a23, w2[k], x23);
        }
        float2 r01 = *reinterpret_cast<float2*>(&a01);
        float2 r23 = *reinterpret_cast<float2*>(&a23);
        ob[(size_t)(b + 0) * bs] = r01.x;
        ob[(size_t)(b + 1) * bs] = r01.y;
        ob[(size_t)(b + 2) * bs] = r23.x;
        ob[(size_t)(b + 3) * bs] = r23.y;
    }
}

// ---------------------------------------------------------------------------
// Routing round (stage 1): CTA = (chunk, b). 256 threads: thread = (o = t>>3,
// q = t&7) owns float4 of d. Per i: coalesced 4KB float4 load, 8-lane shuffle
// dot-reduce for db[o], cooperative softmax over o (warp j handles i=ib+j),
// accumulate c * U into register partial. use_vsum==0 -> uniform c = 1/32.
// ---------------------------------------------------------------------------
__global__ __launch_bounds__(256)
void k_round(int use_vsum) {
    const int ch = blockIdx.x, b = blockIdx.y;
    const int t = threadIdx.x;
    const int o = t >> 3, q = t & 7;
    const int lane = t & 31, w = t >> 5;

    float4 vs = make_float4(0.f, 0.f, 0.f, 0.f);
    if (use_vsum)
        vs = reinterpret_cast<const float4*>(g_vsum)[(b * NO + o) * 8 + q];

    float4 sp = make_float4(0.f, 0.f, 0.f, 0.f);

    __shared__ float s_db[8][NO];
    __shared__ float s_c[8][NO];

    const float4* up = reinterpret_cast<const float4*>(g_uhat) +
                       ((size_t)b * NI + (size_t)ch * IC) * 256 + t;

    for (int ib = 0; ib < IC; ib += 8) {
        float4 U[8];
        #pragma unroll
        for (int j = 0; j < 8; j++)
            U[j] = up[(size_t)(ib + j) * 256];

        if (use_vsum) {
            // phase A: db[o] = vsum[o,:] . u_hat[o,i,:]  (8-lane reduce)
            #pragma unroll
            for (int j = 0; j < 8; j++) {
                float tv = U[j].x * vs.x + U[j].y * vs.y +
                           U[j].z * vs.z + U[j].w * vs.w;
                tv += __shfl_xor_sync(0xffffffffu, tv, 4);
                tv += __shfl_xor_sync(0xffffffffu, tv, 2);
                tv += __shfl_xor_sync(0xffffffffu, tv, 1);
                if (q == 0) s_db[j][o] = tv;
            }
            __syncthreads();
            // phase B: softmax over o — warp w handles i = ib + w, lane = o
            {
                float db = s_db[w][lane];
                float m = db;
                #pragma unroll
                for (int st = 16; st; st >>= 1)
                    m = fmaxf(m, __shfl_xor_sync(0xffffffffu, m, st));
                float e = __expf(db - m);
                float sm = e;
                #pragma unroll
                for (int st = 16; st; st >>= 1)
                    sm += __shfl_xor_sync(0xffffffffu, sm, st);
                s_c[w][lane] = e / sm;
            }
            __syncthreads();
            // phase C: s += c * u_hat
            #pragma unroll
            for (int j = 0; j < 8; j++) {
                float c = s_c[j][o];
                sp.x += c * U[j].x; sp.y += c * U[j].y;
                sp.z += c * U[j].z; sp.w += c * U[j].w;
            }
        } else {
            #pragma unroll
            for (int j = 0; j < 8; j++) {
                sp.x += U[j].x; sp.y += U[j].y;
                sp.z += U[j].z; sp.w += U[j].w;
            }
        }
    }

    if (!use_vsum) {
        const float c = 1.0f / (float)NO;   // softmax(0) over 32 capsules
        sp.x *= c; sp.y *= c; sp.z *= c; sp.w *= c;
    }

    reinterpret_cast<float4*>(g_part)[(b * CH + ch) * 256 + t] = sp;
}

// ---------------------------------------------------------------------------
// Stage 2: reduce chunk partials -> s, squash -> v, update vsum / write out.
// Block per b, 1024 threads: warp = o, lane = d.
// ---------------------------------------------------------------------------
__global__ __launch_bounds__(1024)
void k_stage2(float* __restrict__ out, int round) {
    const int b = blockIdx.x, t = threadIdx.x;
    float s = 0.f;
    #pragma unroll
    for (int c = 0; c < CH; c++)
        s += g_part[(b * CH + c) * (NO * DO) + t];

    float sq = s * s;
    #pragma unroll
    for (int st = 16; st; st >>= 1)
        sq += __shfl_xor_sync(0xffffffffu, sq, st);   // ||s||^2 over d

    float scale = sq / (1.0f + sq) * rsqrtf(sq + 1e-7f);
    float v = s * scale;

    int idx = b * (NO * DO) + t;
    if (round == 2)      out[idx] = v;
    else if (round == 0) g_vsum[idx] = v;
    else                 g_vsum[idx] += v;
}

// ---------------------------------------------------------------------------
extern "C" void kernel_launch(void* const* d_in, const int* in_sizes, int n_in,
                              void* d_out, int out_size) {
    const float* x = (const float*)d_in[0];
    const float* W = (const float*)d_in[1];
    if (in_sizes[0] != B_ * NI * DI) {   // robust to metadata ordering
        x = (const float*)d_in[1];
        W = (const float*)d_in[0];
    }
    float* out = (float*)d_out;

    k1_uhat<<<NI, 1024>>>(x, W);

    dim3 rg(CH, B_);
    k_round<<<rg, 256>>>(0);
    k_stage2<<<B_, NO * DO>>>(out, 0);
    k_round<<<rg, 256>>>(1);
    k_stage2<<<B_, NO * DO>>>(out, 1);
    k_round<<<rg, 256>>>(2);
    k_stage2<<<B_, NO * DO>>>(out, 2);
}

// round 2
// speedup vs baseline: 1.2590x; 1.2590x over previous
#include <cuda_runtime.h>
#include <cuda_fp16.h>
#include <cstdint>

#define B_  64
#define NI  2048
#define DI  16
#define NO  32
#define DO  32
#define CH  16            // i-chunks per (b) for round partials
#define IC  (NI / CH)     // 128 i per chunk

// Scratch (alloc-free rule: __device__ globals)
__device__ __half g_uhat[(size_t)B_ * NI * NO * DO];  // [b][i][o][d]  268 MB fp16
__device__ float  g_part[B_ * CH * NO * DO];          // per-chunk s partials, 4 MB
__device__ float  g_vsum[B_ * NO * DO];               // running sum of v across rounds

// ---------- packed f32x2 helpers (Blackwell FFMA2 via PTX) ----------
__device__ __forceinline__ unsigned long long splat2(float v) {
    unsigned long long r;
    asm("mov.b64 %0, {%1, %1};" : "=l"(r) : "f"(v));
    return r;
}
__device__ __forceinline__ void ffma2(unsigned long long &d,
                                      unsigned long long a, unsigned long long b) {
    asm("fma.rn.f32x2 %0, %1, %2, %0;" : "+l"(d) : "l"(a), "l"(b));
}

// ---------------------------------------------------------------------------
// K1: u_hat[b][i][o][d] = sum_k W[o][i][d][k] * x[b][i][k]   (stored fp16)
// CTA per i (2048 CTAs, 1024 threads). Thread owns (o,d), loops b in packs of 4
// with f32x2 FMAs (two b's per instruction).
// ---------------------------------------------------------------------------
__global__ __launch_bounds__(1024, 1)
void k1_uhat(const float* __restrict__ x, const float* __restrict__ W) {
    const int i = blockIdx.x;
    const int t = threadIdx.x;

    __shared__ __align__(16) float xs[DI][B_];   // [k][b]
    {
        int b = t >> 4, k = t & 15;
        xs[k][b] = x[((size_t)b * NI + i) * DI + k];
    }

    const int o = t >> 5, d = t & 31;
    const float4* wp = reinterpret_cast<const float4*>(W) +
                       ((((size_t)o * NI + i) * DO + d) << 2);   // 16 floats = 4 float4
    float4 wa = wp[0], wb = wp[1], wc = wp[2], wd = wp[3];
    unsigned long long w2[16];
    w2[0]  = splat2(wa.x); w2[1]  = splat2(wa.y); w2[2]  = splat2(wa.z); w2[3]  = splat2(wa.w);
    w2[4]  = splat2(wb.x); w2[5]  = splat2(wb.y); w2[6]  = splat2(wb.z); w2[7]  = splat2(wb.w);
    w2[8]  = splat2(wc.x); w2[9]  = splat2(wc.y); w2[10] = splat2(wc.z); w2[11] = splat2(wc.w);
    w2[12] = splat2(wd.x); w2[13] = splat2(wd.y); w2[14] = splat2(wd.z); w2[15] = splat2(wd.w);

    __syncthreads();

    __half* ob = g_uhat + (size_t)i * (NO * DO) + t;
    const size_t bs = (size_t)NI * NO * DO;   // stride per b in elements

    #pragma unroll 1
    for (int b = 0; b < B_; b += 4) {
        unsigned long long a01 = 0ull, a23 = 0ull;   // {0.f, 0.f}
        #pragma unroll
        for (int k = 0; k < 16; k++) {
            unsigned long long x01 =
                *reinterpret_cast<const unsigned long long*>(&xs[k][b]);
            unsigned long long x23 =
                *reinterpret_cast<const unsigned long long*>(&xs[k][b + 2]);
            ffma2(a01, w2[k], x01);
            ffma2(a23, w2[k], x23);
        }
        float2 r01 = *reinterpret_cast<float2*>(&a01);
        float2 r23 = *reinterpret_cast<float2*>(&a23);
        ob[(size_t)(b + 0) * bs] = __float2half_rn(r01.x);
        ob[(size_t)(b + 1) * bs] = __float2half_rn(r01.y);
        ob[(size_t)(b + 2) * bs] = __float2half_rn(r23.x);
        ob[(size_t)(b + 3) * bs] = __float2half_rn(r23.y);
    }
}

// ---------------------------------------------------------------------------
// Routing round: CTA = (chunk, b). 256 threads: thread = (o = t>>3, q = t&7)
// owns a d-quad (4 halves = uint2). Per i: coalesced 2KB load for the i-slab,
// 8-lane shuffle dot-reduce for db[o], cooperative softmax over o, accumulate
// c * u_hat into fp32 register partial. use_vsum==0 -> uniform c = 1/32.
// ---------------------------------------------------------------------------
__global__ __launch_bounds__(256)
void k_round(int use_vsum) {
    const int ch = blockIdx.x, b = blockIdx.y;
    const int t = threadIdx.x;
    const int o = t >> 3, q = t & 7;
    const int lane = t & 31, w = t >> 5;

    float4 vs = make_float4(0.f, 0.f, 0.f, 0.f);
    if (use_vsum)
        vs = reinterpret_cast<const float4*>(g_vsum)[(b * NO + o) * 8 + q];

    float4 sp = make_float4(0.f, 0.f, 0.f, 0.f);

    __shared__ float s_db[8][NO];
    __shared__ float s_c[8][NO];

    const uint2* up = reinterpret_cast<const uint2*>(g_uhat) +
                      ((size_t)b * NI + (size_t)ch * IC) * 256 + t;

    for (int ib = 0; ib < IC; ib += 8) {
        float4 U[8];
        #pragma unroll
        for (int j = 0; j < 8; j++) {
            uint2 raw = up[(size_t)(ib + j) * 256];
            float2 f01 = __half22float2(*reinterpret_cast<__half2*>(&raw.x));
            float2 f23 = __half22float2(*reinterpret_cast<__half2*>(&raw.y));
            U[j] = make_float4(f01.x, f01.y, f23.x, f23.y);
        }

        if (use_vsum) {
            // phase A: db[o] = vsum[o,:] . u_hat[o,i,:]  (8-lane reduce)
            #pragma unroll
            for (int j = 0; j < 8; j++) {
                float tv = U[j].x * vs.x + U[j].y * vs.y +
                           U[j].z * vs.z + U[j].w * vs.w;
                tv += __shfl_xor_sync(0xffffffffu, tv, 4);
                tv += __shfl_xor_sync(0xffffffffu, tv, 2);
                tv += __shfl_xor_sync(0xffffffffu, tv, 1);
                if (q == 0) s_db[j][o] = tv;
            }
            __syncthreads();
            // phase B: softmax over o — warp w handles i = ib + w, lane = o
            {
                float db = s_db[w][lane];
                float m = db;
                #pragma unroll
                for (int st = 16; st; st >>= 1)
                    m = fmaxf(m, __shfl_xor_sync(0xffffffffu, m, st));
                float e = __expf(db - m);
                float sm = e;
                #pragma unroll
                for (int st = 16; st; st >>= 1)
                    sm += __shfl_xor_sync(0xffffffffu, sm, st);
                s_c[w][lane] = e / sm;
            }
            __syncthreads();
            // phase C: s += c * u_hat
            #pragma unroll
            for (int j = 0; j < 8; j++) {
                float c = s_c[j][o];
                sp.x += c * U[j].x; sp.y += c * U[j].y;
                sp.z += c * U[j].z; sp.w += c * U[j].w;
            }
        } else {
            #pragma unroll
            for (int j = 0; j < 8; j++) {
                sp.x += U[j].x; sp.y += U[j].y;
                sp.z += U[j].z; sp.w += U[j].w;
            }
        }
    }

    if (!use_vsum) {
        const float c = 1.0f / (float)NO;   // softmax(0) over 32 capsules
        sp.x *= c; sp.y *= c; sp.z *= c; sp.w *= c;
    }

    reinterpret_cast<float4*>(g_part)[(b * CH + ch) * 256 + t] = sp;
}

// ---------------------------------------------------------------------------
// Stage 2: reduce chunk partials -> s, squash -> v, update vsum / write out.
// Block per b, 1024 threads: warp = o, lane = d.
// ---------------------------------------------------------------------------
__global__ __launch_bounds__(1024)
void k_stage2(float* __restrict__ out, int round) {
    const int b = blockIdx.x, t = threadIdx.x;
    float s = 0.f;
    #pragma unroll
    for (int c = 0; c < CH; c++)
        s += g_part[(b * CH + c) * (NO * DO) + t];

    float sq = s * s;
    #pragma unroll
    for (int st = 16; st; st >>= 1)
        sq += __shfl_xor_sync(0xffffffffu, sq, st);   // ||s||^2 over d

    float scale = sq / (1.0f + sq) * rsqrtf(sq + 1e-7f);
    float v = s * scale;

    int idx = b * (NO * DO) + t;
    if (round == 2)      out[idx] = v;
    else if (round == 0) g_vsum[idx] = v;
    else                 g_vsum[idx] += v;
}

// ---------------------------------------------------------------------------
extern "C" void kernel_launch(void* const* d_in, const int* in_sizes, int n_in,
                              void* d_out, int out_size) {
    const float* x = (const float*)d_in[0];
    const float* W = (const float*)d_in[1];
    if (in_sizes[0] != B_ * NI * DI) {   // robust to metadata ordering
        x = (const float*)d_in[1];
        W = (const float*)d_in[0];
    }
    float* out = (float*)d_out;

    k1_uhat<<<NI, 1024>>>(x, W);

    dim3 rg(CH, B_);
    k_round<<<rg, 256>>>(0);
    k_stage2<<<B_, NO * DO>>>(out, 0);
    k_round<<<rg, 256>>>(1);
    k_stage2<<<B_, NO * DO>>>(out, 1);
    k_round<<<rg, 256>>>(2);
    k_stage2<<<B_, NO * DO>>>(out, 2);
}

// round 3
// speedup vs baseline: 1.4478x; 1.1500x over previous
#include <cuda_runtime.h>
#include <cuda_fp16.h>
#include <cstdint>

#define B_  64
#define NI  2048
#define DI  16
#define NO  32
#define DO  32
#define CH  16            // i-chunks per (b) for round partials
#define IC  (NI / CH)     // 128 i per chunk

// Scratch (alloc-free rule: __device__ globals)
__device__ __half g_uhat[(size_t)B_ * NI * NO * DO];  // [b][i][o][d]  268 MB fp16
__device__ float  g_part[B_ * CH * NO * DO];          // per-chunk s partials, 4 MB
__device__ float  g_vsum[B_ * NO * DO];               // running sum of v across rounds

// ---------- packed f32x2 helpers (Blackwell FFMA2 via PTX) ----------
__device__ __forceinline__ unsigned long long splat2(float v) {
    unsigned long long r;
    asm("mov.b64 %0, {%1, %1};" : "=l"(r) : "f"(v));
    return r;
}
__device__ __forceinline__ void ffma2(unsigned long long &d,
                                      unsigned long long a, unsigned long long b) {
    asm("fma.rn.f32x2 %0, %1, %2, %0;" : "+l"(d) : "l"(a), "l"(b));
}
__device__ __forceinline__ float2 unpack2(unsigned long long v) {
    float2 f;
    asm("mov.b64 {%0, %1}, %2;" : "=f"(f.x), "=f"(f.y) : "l"(v));
    return f;
}

// ---------------------------------------------------------------------------
// K1: u_hat[b][i][o][d] = sum_k W[o][i][d][k] * x[b][i][k]   (stored fp16)
// CTA per i (2048 CTAs, 512 threads). Thread owns (o, d-pair); W splats held in
// 32 u64 regs amortized over all 64 b. Inner (k, b-quad): 1 LDS.128 + 4 FFMA2.
// Stores: packed half2 (d0,d1) per b -> STG.32.
// ---------------------------------------------------------------------------
__global__ __launch_bounds__(512, 1)
void k1_uhat(const float* __restrict__ x, const float* __restrict__ W) {
    const int i = blockIdx.x;
    const int t = threadIdx.x;

    __shared__ __align__(16) float xs[DI][B_];   // [k][b], rows 256B
    {
        int idx = t;
        #pragma unroll
        for (int r = 0; r < 2; r++, idx += 512) {
            int b = idx >> 4, k = idx & 15;
            xs[k][b] = x[((size_t)b * NI + i) * DI + k];
        }
    }

    const int o = t >> 4, dp = t & 15;           // d = 2dp, 2dp+1
    const float4* wp = reinterpret_cast<const float4*>(W) +
                       ((((size_t)o * NI + i) * DO + 2 * dp) * DI >> 2);
    float4 qa = wp[0], qb = wp[1], qc = wp[2], qd = wp[3];   // W[o,i,2dp,0..15]
    float4 qe = wp[4], qf = wp[5], qg = wp[6], qh = wp[7];   // W[o,i,2dp+1,0..15]

    unsigned long long w0[16], w1[16];
    w0[0]=splat2(qa.x); w0[1]=splat2(qa.y); w0[2]=splat2(qa.z); w0[3]=splat2(qa.w);
    w0[4]=splat2(qb.x); w0[5]=splat2(qb.y); w0[6]=splat2(qb.z); w0[7]=splat2(qb.w);
    w0[8]=splat2(qc.x); w0[9]=splat2(qc.y); w0[10]=splat2(qc.z); w0[11]=splat2(qc.w);
    w0[12]=splat2(qd.x); w0[13]=splat2(qd.y); w0[14]=splat2(qd.z); w0[15]=splat2(qd.w);
    w1[0]=splat2(qe.x); w1[1]=splat2(qe.y); w1[2]=splat2(qe.z); w1[3]=splat2(qe.w);
    w1[4]=splat2(qf.x); w1[5]=splat2(qf.y); w1[6]=splat2(qf.z); w1[7]=splat2(qf.w);
    w1[8]=splat2(qg.x); w1[9]=splat2(qg.y); w1[10]=splat2(qg.z); w1[11]=splat2(qg.w);
    w1[12]=splat2(qh.x); w1[13]=splat2(qh.y); w1[14]=splat2(qh.z); w1[15]=splat2(qh.w);

    __syncthreads();

    __half2* ob = reinterpret_cast<__half2*>(g_uhat) +
                  (size_t)i * 512 + o * 16 + dp;
    const size_t bs2 = (size_t)NI * NO * DO / 2;   // half2 stride per b

    #pragma unroll 1
    for (int bq = 0; bq < 16; bq++) {
        const int b = bq * 4;
        unsigned long long a0p = 0ull, a0q = 0ull;   // d0: {b,b+1}, {b+2,b+3}
        unsigned long long a1p = 0ull, a1q = 0ull;   // d1
        #pragma unroll
        for (int k = 0; k < 16; k++) {
            ulonglong2 xq = *reinterpret_cast<const ulonglong2*>(&xs[k][b]);
            ffma2(a0p, w0[k], xq.x);
            ffma2(a0q, w0[k], xq.y);
            ffma2(a1p, w1[k], xq.x);
            ffma2(a1q, w1[k], xq.y);
        }
        float2 f0p = unpack2(a0p), f0q = unpack2(a0q);
        float2 f1p = unpack2(a1p), f1q = unpack2(a1q);
        ob[(size_t)(b + 0) * bs2] = __float22half2_rn(make_float2(f0p.x, f1p.x));
        ob[(size_t)(b + 1) * bs2] = __float22half2_rn(make_float2(f0p.y, f1p.y));
        ob[(size_t)(b + 2) * bs2] = __float22half2_rn(make_float2(f0q.x, f1q.x));
        ob[(size_t)(b + 3) * bs2] = __float22half2_rn(make_float2(f0q.y, f1q.y));
    }
}

// ---------------------------------------------------------------------------
// Routing round: CTA = (chunk, b), 256 threads.
// Warp covers 8 o x 4 q (q owns 8 d => all 32 d of an (o,i) inside one warp).
// Batch = 8 i: warps 0-3 process i=ib..ib+3, warps 4-7 process ib+4..ib+7.
// Floats converted in phase A persist in regs and are reused in phase C.
// ---------------------------------------------------------------------------
__global__ __launch_bounds__(256)
void k_round(int use_vsum) {
    const int ch = blockIdx.x, b = blockIdx.y;
    const int t = threadIdx.x;
    const int w = t >> 5, lane = t & 31;
    const int o = ((w & 3) << 3) + (lane >> 2);
    const int q = lane & 3;                 // owns d = 8q .. 8q+7
    const int half = w >> 2;                // i-subgroup within batch

    float vs[8];
    if (use_vsum) {
        const float4* vp = reinterpret_cast<const float4*>(
            g_vsum + (b * NO + o) * DO + q * 8);
        float4 va = vp[0], vb = vp[1];
        vs[0]=va.x; vs[1]=va.y; vs[2]=va.z; vs[3]=va.w;
        vs[4]=vb.x; vs[5]=vb.y; vs[6]=vb.z; vs[7]=vb.w;
    }

    float sp[8];
    #pragma unroll
    for (int d = 0; d < 8; d++) sp[d] = 0.f;

    __shared__ float s_db[8][NO];
    __shared__ float s_c[8][NO];

    // uint4 = 8 halves; 128 uint4 per i
    const uint4* up = reinterpret_cast<const uint4*>(g_uhat) +
                      ((size_t)b * NI + (size_t)ch * IC) * 128 + o * 4 + q;

    #pragma unroll 1
    for (int ib = 0; ib < IC; ib += 8) {
        uint4 raw[4];
        #pragma unroll
        for (int v = 0; v < 4; v++)
            raw[v] = up[(size_t)(ib + half * 4 + v) * 128];

        float F[4][8];
        #pragma unroll
        for (int v = 0; v < 4; v++) {
            float2 fa = __half22float2(*reinterpret_cast<__half2*>(&raw[v].x));
            float2 fb = __half22float2(*reinterpret_cast<__half2*>(&raw[v].y));
            float2 fc = __half22float2(*reinterpret_cast<__half2*>(&raw[v].z));
            float2 fd = __half22float2(*reinterpret_cast<__half2*>(&raw[v].w));
            F[v][0]=fa.x; F[v][1]=fa.y; F[v][2]=fb.x; F[v][3]=fb.y;
            F[v][4]=fc.x; F[v][5]=fc.y; F[v][6]=fd.x; F[v][7]=fd.y;
        }

        if (use_vsum) {
            // phase A: db[o,i] = vsum . u_hat (reduce over 4 q-lanes)
            #pragma unroll
            for (int v = 0; v < 4; v++) {
                float tdb = F[v][0]*vs[0] + F[v][1]*vs[1] + F[v][2]*vs[2] +
                            F[v][3]*vs[3] + F[v][4]*vs[4] + F[v][5]*vs[5] +
                            F[v][6]*vs[6] + F[v][7]*vs[7];
                tdb += __shfl_xor_sync(0xffffffffu, tdb, 2);
                tdb += __shfl_xor_sync(0xffffffffu, tdb, 1);
                if (q == 0) s_db[half * 4 + v][o] = tdb;
            }
            __syncthreads();
            // phase B: softmax over o; warp w handles i_local = w, lane = o
            {
                float db = s_db[w][lane];
                float m = db;
                #pragma unroll
                for (int st = 16; st; st >>= 1)
                    m = fmaxf(m, __shfl_xor_sync(0xffffffffu, m, st));
                float e = __expf(db - m);
                float sm = e;
                #pragma unroll
                for (int st = 16; st; st >>= 1)
                    sm += __shfl_xor_sync(0xffffffffu, sm, st);
                s_c[w][lane] = e / sm;
            }
            __syncthreads();
            // phase C: s += c * u_hat (reuse F floats)
            #pragma unroll
            for (int v = 0; v < 4; v++) {
                float c = s_c[half * 4 + v][o];
                #pragma unroll
                for (int d = 0; d < 8; d++) sp[d] += c * F[v][d];
            }
        } else {
            #pragma unroll
            for (int v = 0; v < 4; v++)
                #pragma unroll
                for (int d = 0; d < 8; d++) sp[d] += F[v][d];
        }
    }

    if (!use_vsum) {
        const float c = 1.0f / (float)NO;
        #pragma unroll
        for (int d = 0; d < 8; d++) sp[d] *= c;
    }

    // Each thread covered 4 of 8 i per batch; the other half-group covered the
    // rest. Partials are disjoint over i between half=0 and half=1 threads with
    // the same (o,q)? No — both halves accumulated DIFFERENT i for the SAME
    // (o,q,d). Combine the two half-groups via shared memory.
    __shared__ float s_red[256 * 8];
    #pragma unroll
    for (int d = 0; d < 8; d++)
        s_red[(t & 127) * 8 + d + (half ? 1024 : 0)] = sp[d];
    __syncthreads();
    if (half == 0) {
        float4* pp = reinterpret_cast<float4*>(
            g_part + ((b * CH + ch) * (NO * DO)) + o * DO + q * 8);
        float4 r0, r1;
        int base = (t & 127) * 8;
        r0.x = s_red[base+0] + s_red[base+0+1024];
        r0.y = s_red[base+1] + s_red[base+1+1024];
        r0.z = s_red[base+2] + s_red[base+2+1024];
        r0.w = s_red[base+3] + s_red[base+3+1024];
        r1.x = s_red[base+4] + s_red[base+4+1024];
        r1.y = s_red[base+5] + s_red[base+5+1024];
        r1.z = s_red[base+6] + s_red[base+6+1024];
        r1.w = s_red[base+7] + s_red[base+7+1024];
        pp[0] = r0; pp[1] = r1;
    }
}

// ---------------------------------------------------------------------------
// Stage 2: reduce chunk partials -> s, squash -> v, update vsum / write out.
// Block per b, 1024 threads: warp = o, lane = d.
// ---------------------------------------------------------------------------
__global__ __launch_bounds__(1024)
void k_stage2(float* __restrict__ out, int round) {
    const int b = blockIdx.x, t = threadIdx.x;
    float s = 0.f;
    #pragma unroll
    for (int c = 0; c < CH; c++)
        s += g_part[(b * CH + c) * (NO * DO) + t];

    float sq = s * s;
    #pragma unroll
    for (int st = 16; st; st >>= 1)
        sq += __shfl_xor_sync(0xffffffffu, sq, st);   // ||s||^2 over d

    float scale = sq / (1.0f + sq) * rsqrtf(sq + 1e-7f);
    float v = s * scale;

    int idx = b * (NO * DO) + t;
    if (round == 2)      out[idx] = v;
    else if (round == 0) g_vsum[idx] = v;
    else                 g_vsum[idx] += v;
}

// ---------------------------------------------------------------------------
extern "C" void kernel_launch(void* const* d_in, const int* in_sizes, int n_in,
                              void* d_out, int out_size) {
    const float* x = (const float*)d_in[0];
    const float* W = (const float*)d_in[1];
    if (in_sizes[0] != B_ * NI * DI) {   // robust to metadata ordering
        x = (const float*)d_in[1];
        W = (const float*)d_in[0];
    }
    float* out = (float*)d_out;

    k1_uhat<<<NI, 512>>>(x, W);

    dim3 rg(CH, B_);
    k_round<<<rg, 256>>>(0);
    k_stage2<<<B_, NO * DO>>>(out, 0);
    k_round<<<rg, 256>>>(1);
    k_stage2<<<B_, NO * DO>>>(out, 1);
    k_round<<<rg, 256>>>(2);
    k_stage2<<<B_, NO * DO>>>(out, 2);
}